// round 12
// baseline (speedup 1.0000x reference)
#include <cuda_runtime.h>
#include <math.h>

#define B 16
#define N 32
#define C 512
#define FEAT 224

#define HW0 784
#define HW1 196
#define HW2 49
#define OUT_ROW (C*(HW0+HW1+HW2))
#define OUT_OFF1 (C*HW0)         // 401408
#define OUT_OFF2 (C*(HW0+HW1))   // 501760
#define MAXSEG 96

// ---------------- scratch (no allocations allowed) ----------------
__device__ float    g_sum28[B][HW0];   // per-8x8-tile sum of sigmoid
__device__ float    g_logits[3 * B * C];
__device__ float    g_weights[3 * B * C];
__device__ int      g_cnt[3 * B];      // zero-init; reset by last block each run

// ---------------- K0: full conf path, one block per batch ---------------
// grid = B, 256 threads. Builds the x-segment table ONCE, all 224 row
// masks in one pass, merges rows per 8-row band, then evaluates
// area-weighted sigmoid rectangles into all 784 tile sums.
__global__ void conf_kernel(const float* __restrict__ confs,
                            const float* __restrict__ boxes) {
    int b = blockIdx.x;
    int t = threadIdx.x;
    int lane = t & 31, wl = t >> 5;

    __shared__ int sbx[N * 4];
    __shared__ float sconf[N];
    __shared__ unsigned char flag[FEAT];
    __shared__ int segstart[MAXSEG];
    __shared__ int woff[8];
    __shared__ int snx;
    __shared__ float swx[MAXSEG];
    __shared__ unsigned scolm[MAXSEG];
    __shared__ int scell[MAXSEG];
    __shared__ unsigned rowm[FEAT];
    __shared__ unsigned srowm[28][8];
    __shared__ float swy[28][8];
    __shared__ int sny[28];
    __shared__ float stile[HW0];

    if (t < N * 4) sbx[t] = (int)floorf(boxes[b * N * 4 + t] * (float)FEAT);
    if (t < N) sconf[t] = confs[b * N + t];
    if (t < FEAT) flag[t] = ((t & 7) == 0);
    for (int i = t; i < HW0; i += 256) stile[i] = 0.f;
    __syncthreads();

    if (t < N) {
        int e1 = sbx[4 * t], e2 = sbx[4 * t + 2];
        if (e1 >= 0 && e1 < FEAT) flag[e1] = 1;
        if (e2 >= 0 && e2 < FEAT) flag[e2] = 1;
    }
    __syncthreads();

    // compact x-breakpoints via ballot-scan (warps 0..6 cover 224 positions)
    unsigned bal = 0;
    if (t < FEAT) {
        bal = __ballot_sync(0xffffffffu, flag[t] != 0);
        if (lane == 0) woff[wl] = __popc(bal);
    }
    // row masks for all 224 rows in parallel
    if (t < FEAT) {
        unsigned rm = 0;
#pragma unroll
        for (int n = 0; n < N; n++)
            rm |= (unsigned)(t >= sbx[4 * n + 1] && t < sbx[4 * n + 3]) << n;
        rowm[t] = rm;
    }
    __syncthreads();
    if (t == 0) {
        int run = 0;
        for (int i = 0; i < 7; i++) { int c = woff[i]; woff[i] = run; run += c; }
        snx = run;
    }
    // per-band row merge (28 threads, 8 serial iters each)
    if (t < 28) {
        int ny = 0;
        unsigned prev = 0xffffffffu;
        for (int i = 0; i < 8; i++) {
            unsigned rm = rowm[t * 8 + i];
            if (i == 0 || rm != prev) {
                srowm[t][ny] = rm;
                swy[t][ny] = 1.f;
                ny++;
            } else {
                swy[t][ny - 1] += 1.f;
            }
            prev = rm;
        }
        sny[t] = ny;
    }
    __syncthreads();
    if (t < FEAT && flag[t])
        segstart[woff[wl] + __popc(bal & ((1u << lane) - 1u))] = t;
    __syncthreads();

    int nx = snx;
    if (t < nx) {
        int s = segstart[t];
        swx[t] = (float)(((t + 1 < nx) ? segstart[t + 1] : FEAT) - s);
        unsigned m = 0;
#pragma unroll
        for (int n = 0; n < N; n++)
            m |= (unsigned)(s >= sbx[4 * n] && s < sbx[4 * n + 2]) << n;
        scolm[t] = m;
        scell[t] = s >> 3;
    }
    __syncthreads();

    // rectangle evaluation over all bands (atomics, no syncs needed)
    for (int band = 0; band < 28; band++) {
        int ny = sny[band];
        int pairs = nx * ny;
        for (int p = t; p < pairs; p += 256) {
            int ys = p / nx, xs = p - ys * nx;
            unsigned m = srowm[band][ys] & scolm[xs];
            float v = 0.f;
            while (m) {
                int i = __ffs(m) - 1;
                v += sconf[i];
                m &= m - 1;
            }
            float sg = __fdividef(1.f, 1.f + __expf(-v));
            atomicAdd(&stile[band * 28 + scell[xs]], swy[band][ys] * swx[xs] * sg);
        }
    }
    __syncthreads();
    for (int i = t; i < HW0; i += 256) g_sum28[b][i] = stile[i];
}

// -------- K1: logits (2 channels/warp) + last-block softmax epilogue ------
// grid = (C/16, B, 3), 256 threads = 8 warps; each warp does 2 channels.
__global__ void logits_kernel(const float* __restrict__ f0,
                              const float* __restrict__ f1,
                              const float* __restrict__ f2) {
    int l = blockIdx.z, b = blockIdx.y;
    __shared__ __align__(16) float satt[HW0];

    int warp = threadIdx.x >> 5, lane = threadIdx.x & 31;
    int c0 = blockIdx.x * 16 + warp * 2;
    int t = threadIdx.x;
    float acc0 = 0.f, acc1 = 0.f;
    const float* gs = g_sum28[b];

    if (l == 0) {
        for (int i = t; i < HW0; i += 256) satt[i] = gs[i] * (1.f / 64.f);
        __syncthreads();
        const float4* fp0 = (const float4*)(f0 + ((size_t)(b * C + c0)) * HW0);
        const float4* fp1 = fp0 + (HW0 / 4);
        const float4* ap = (const float4*)satt;
#pragma unroll
        for (int k = 0; k < 7; k++) {
            int i = lane + 32 * k;
            if (i < HW0 / 4) {
                float4 v0 = fp0[i], v1 = fp1[i], a = ap[i];
                acc0 = fmaf(v0.x, a.x, acc0);
                acc0 = fmaf(v0.y, a.y, acc0);
                acc0 = fmaf(v0.z, a.z, acc0);
                acc0 = fmaf(v0.w, a.w, acc0);
                acc1 = fmaf(v1.x, a.x, acc1);
                acc1 = fmaf(v1.y, a.y, acc1);
                acc1 = fmaf(v1.z, a.z, acc1);
                acc1 = fmaf(v1.w, a.w, acc1);
            }
        }
    } else if (l == 1) {
        if (t < HW1) {
            int ay = t / 14, ax = t % 14;
            int base = (2 * ay) * 28 + 2 * ax;
            float s = gs[base] + gs[base + 1] + gs[base + 28] + gs[base + 29];
            satt[t] = s * (1.f / 256.f);
        }
        __syncthreads();
        const float4* fp0 = (const float4*)(f1 + ((size_t)(b * C + c0)) * HW1);
        const float4* fp1 = fp0 + (HW1 / 4);
        const float4* ap = (const float4*)satt;
#pragma unroll
        for (int k = 0; k < 2; k++) {
            int i = lane + 32 * k;
            if (i < HW1 / 4) {
                float4 v0 = fp0[i], v1 = fp1[i], a = ap[i];
                acc0 = fmaf(v0.x, a.x, acc0);
                acc0 = fmaf(v0.y, a.y, acc0);
                acc0 = fmaf(v0.z, a.z, acc0);
                acc0 = fmaf(v0.w, a.w, acc0);
                acc1 = fmaf(v1.x, a.x, acc1);
                acc1 = fmaf(v1.y, a.y, acc1);
                acc1 = fmaf(v1.z, a.z, acc1);
                acc1 = fmaf(v1.w, a.w, acc1);
            }
        }
    } else {
        if (t < HW2) {
            int ay = t / 7, ax = t % 7;
            float s = 0.f;
#pragma unroll
            for (int iy = 0; iy < 4; iy++)
#pragma unroll
                for (int ix = 0; ix < 4; ix++)
                    s += gs[(4 * ay + iy) * 28 + 4 * ax + ix];
            satt[t] = s * (1.f / 1024.f);
        }
        __syncthreads();
        const float* fp0 = f2 + ((size_t)(b * C + c0)) * HW2;
        const float* fp1 = fp0 + HW2;
#pragma unroll
        for (int k = 0; k < 2; k++) {
            int i = lane + 32 * k;
            if (i < HW2) {
                float a = satt[i];
                acc0 = fmaf(fp0[i], a, acc0);
                acc1 = fmaf(fp1[i], a, acc1);
            }
        }
    }

#pragma unroll
    for (int o = 16; o > 0; o >>= 1) {
        acc0 += __shfl_xor_sync(0xffffffffu, acc0, o);
        acc1 += __shfl_xor_sync(0xffffffffu, acc1, o);
    }
    int base = (l * B + b) * C;
    if (lane == 0) {
        g_logits[base + c0] = acc0;
        g_logits[base + c0 + 1] = acc1;
    }
    __syncthreads();

    // ---- last-block softmax epilogue ----
    __shared__ int is_last;
    if (t == 0) {
        __threadfence();
        is_last = (atomicAdd(&g_cnt[l * B + b], 1) == (C / 16) - 1);
    }
    __syncthreads();
    if (!is_last) return;
    if (t == 0) g_cnt[l * B + b] = 0;   // reset for next graph replay

    __shared__ float red[8];
    __shared__ float smax, ssum;
    float x0 = g_logits[base + t];
    float x1 = g_logits[base + t + 256];
    float m = fmaxf(x0, x1);
#pragma unroll
    for (int o = 16; o > 0; o >>= 1) m = fmaxf(m, __shfl_xor_sync(0xffffffffu, m, o));
    if (lane == 0) red[warp] = m;
    __syncthreads();
    if (t == 0) {
        float mm = red[0];
#pragma unroll
        for (int i = 1; i < 8; i++) mm = fmaxf(mm, red[i]);
        smax = mm;
    }
    __syncthreads();
    float e0 = __expf(x0 - smax), e1 = __expf(x1 - smax);
    float s = e0 + e1;
#pragma unroll
    for (int o = 16; o > 0; o >>= 1) s += __shfl_xor_sync(0xffffffffu, s, o);
    if (lane == 0) red[warp] = s;
    __syncthreads();
    if (t == 0) {
        float ss = 0.f;
#pragma unroll
        for (int i = 0; i < 8; i++) ss += red[i];
        ssum = ss;
    }
    __syncthreads();
    float inv = __fdividef(1.f, ssum);
    g_weights[base + t] = e0 * inv;
    g_weights[base + t + 256] = e1 * inv;
}

// ---------------- K2: pure streaming scale, warp-per-row -----------------
__global__ void scale_kernel(const float* __restrict__ f0,
                             const float* __restrict__ f1,
                             const float* __restrict__ f2,
                             float* __restrict__ out) {
    int l = blockIdx.y;
    int warp = threadIdx.x >> 5, lane = threadIdx.x & 31;
    int row = blockIdx.x * 16 + warp;   // 0 .. B*C-1
    int b = row >> 9, c = row & (C - 1);
    float w = __ldg(&g_weights[(l * B + b) * C + c]);

    if (l == 0) {
        const float4* src = (const float4*)(f0 + (size_t)row * HW0);
        float4* dst = (float4*)(out + (size_t)b * OUT_ROW + (size_t)c * HW0);
#pragma unroll
        for (int k = 0; k < 7; k++) {
            int i = lane + 32 * k;
            if (i < HW0 / 4) {
                float4 v = src[i];
                v.x *= w; v.y *= w; v.z *= w; v.w *= w;
                __stcs(&dst[i], v);
            }
        }
    } else if (l == 1) {
        const float4* src = (const float4*)(f1 + (size_t)row * HW1);
        float4* dst = (float4*)(out + (size_t)b * OUT_ROW + OUT_OFF1 + (size_t)c * HW1);
#pragma unroll
        for (int k = 0; k < 2; k++) {
            int i = lane + 32 * k;
            if (i < HW1 / 4) {
                float4 v = src[i];
                v.x *= w; v.y *= w; v.z *= w; v.w *= w;
                __stcs(&dst[i], v);
            }
        }
    } else {
        const float* src = f2 + (size_t)row * HW2;
        float* dst = out + (size_t)b * OUT_ROW + OUT_OFF2 + (size_t)c * HW2;
#pragma unroll
        for (int k = 0; k < 2; k++) {
            int i = lane + 32 * k;
            if (i < HW2) __stcs(&dst[i], src[i] * w);
        }
    }
}

extern "C" void kernel_launch(void* const* d_in, const int* in_sizes, int n_in,
                              void* d_out, int out_size) {
    const float* confs = (const float*)d_in[0];
    const float* boxes = (const float*)d_in[1];
    const float* f0 = (const float*)d_in[2];
    const float* f1 = (const float*)d_in[3];
    const float* f2 = (const float*)d_in[4];
    float* out = (float*)d_out;

    conf_kernel<<<B, 256>>>(confs, boxes);
    logits_kernel<<<dim3(C / 16, B, 3), 256>>>(f0, f1, f2);
    scale_kernel<<<dim3(B * C / 16, 3), 512>>>(f0, f1, f2, out);
}

// round 13
// speedup vs baseline: 1.8668x; 1.8668x over previous
#include <cuda_runtime.h>
#include <math.h>

#define B 16
#define N 32
#define C 512
#define FEAT 224

#define HW0 784
#define HW1 196
#define HW2 49
#define OUT_ROW (C*(HW0+HW1+HW2))
#define OUT_OFF1 (C*HW0)         // 401408
#define OUT_OFF2 (C*(HW0+HW1))   // 501760
#define MAXSEG 96

// ---------------- scratch (no allocations allowed) ----------------
__device__ float g_sum28[B][HW0];   // per-8x8-tile sum of sigmoid
__device__ float g_logits[3 * B * C];
__device__ float g_weights[3 * B * C];
__device__ int   g_cnt[3 * B];      // zero-init; reset by last block each run

// ---------------- K1: tile kernel with inline x-segment build -----------
// grid = (28 bands, B), 256 threads. Each block: builds the x-segment table
// via ballot-scan (redundant across bands of a batch, but fully parallel),
// computes+merges the band's 8 row masks, then evaluates area-weighted
// sigmoid rectangles into 28 tile sums.
__global__ void tile_kernel(const float* __restrict__ confs,
                            const float* __restrict__ boxes) {
    int band = blockIdx.x, b = blockIdx.y;
    int t = threadIdx.x;
    int lane = t & 31, wl = t >> 5;

    __shared__ int sbx[N * 4];
    __shared__ float sconf[N];
    __shared__ unsigned char flag[FEAT];
    __shared__ int segstart[MAXSEG];
    __shared__ int woff[8];
    __shared__ int snx, sny;
    __shared__ float swx[MAXSEG];
    __shared__ unsigned scolm[MAXSEG];
    __shared__ int scell[MAXSEG];
    __shared__ unsigned rm8[8];
    __shared__ float swy[8];
    __shared__ unsigned srowm[8];
    __shared__ float stile[28];

    if (t < N * 4) sbx[t] = (int)floorf(boxes[b * N * 4 + t] * (float)FEAT);
    if (t < N) sconf[t] = confs[b * N + t];
    if (t < 28) stile[t] = 0.f;
    if (t < FEAT) flag[t] = ((t & 7) == 0);
    __syncthreads();

    if (t < N) {
        int e1 = sbx[4 * t], e2 = sbx[4 * t + 2];
        if (e1 >= 0 && e1 < FEAT) flag[e1] = 1;
        if (e2 >= 0 && e2 < FEAT) flag[e2] = 1;
    }
    // row masks for this band's 8 pixel rows (independent of flags)
    if (t >= 32 && t < 40) {
        int i = t - 32;
        int y = band * 8 + i;
        unsigned rm = 0;
#pragma unroll
        for (int n = 0; n < N; n++)
            rm |= (unsigned)(y >= sbx[4 * n + 1] && y < sbx[4 * n + 3]) << n;
        rm8[i] = rm;
    }
    __syncthreads();

    unsigned bal = 0;
    if (t < FEAT) {                 // warps 0..6, all lanes active
        bal = __ballot_sync(0xffffffffu, flag[t] != 0);
        if (lane == 0) woff[wl] = __popc(bal);
    }
    __syncthreads();
    if (t == 0) {
        int run = 0;
        for (int i = 0; i < 7; i++) { int c = woff[i]; woff[i] = run; run += c; }
        snx = run;
    }
    if (t == 32) {                  // warp 1: merge equal adjacent row masks
        int ny = 0;
        unsigned prev = 0xffffffffu;
#pragma unroll
        for (int i = 0; i < 8; i++) {
            unsigned rm = rm8[i];
            if (i == 0 || rm != prev) {
                srowm[ny] = rm;
                swy[ny] = 1.f;
                ny++;
            } else {
                swy[ny - 1] += 1.f;
            }
            prev = rm;
        }
        sny = ny;
    }
    __syncthreads();
    if (t < FEAT && flag[t])
        segstart[woff[wl] + __popc(bal & ((1u << lane) - 1u))] = t;
    __syncthreads();

    int nx = snx;
    if (t < nx) {
        int s = segstart[t];
        swx[t] = (float)(((t + 1 < nx) ? segstart[t + 1] : FEAT) - s);
        unsigned m = 0;
#pragma unroll
        for (int n = 0; n < N; n++)
            m |= (unsigned)(s >= sbx[4 * n] && s < sbx[4 * n + 2]) << n;
        scolm[t] = m;
        scell[t] = s >> 3;
    }
    __syncthreads();

    int ny = sny;
    int pairs = nx * ny;
    for (int p = t; p < pairs; p += 256) {
        int ys = p / nx, xs = p - ys * nx;
        unsigned m = srowm[ys] & scolm[xs];
        float v = 0.f;
        while (m) {
            int i = __ffs(m) - 1;
            v += sconf[i];
            m &= m - 1;
        }
        float sg = __fdividef(1.f, 1.f + __expf(-v));
        atomicAdd(&stile[scell[xs]], swy[ys] * swx[xs] * sg);
    }
    __syncthreads();
    if (t < 28) g_sum28[b][band * 28 + t] = stile[t];
}

// -------- K2: logits (2 channels/warp) + last-block softmax epilogue ------
// grid = (C/16, B, 3), 256 threads = 8 warps; each warp does 2 channels.
__global__ void logits_kernel(const float* __restrict__ f0,
                              const float* __restrict__ f1,
                              const float* __restrict__ f2) {
    int l = blockIdx.z, b = blockIdx.y;
    __shared__ __align__(16) float satt[HW0];

    int warp = threadIdx.x >> 5, lane = threadIdx.x & 31;
    int c0 = blockIdx.x * 16 + warp * 2;
    int t = threadIdx.x;
    float acc0 = 0.f, acc1 = 0.f;
    const float* gs = g_sum28[b];

    if (l == 0) {
        for (int i = t; i < HW0; i += 256) satt[i] = gs[i] * (1.f / 64.f);
        __syncthreads();
        const float4* fp0 = (const float4*)(f0 + ((size_t)(b * C + c0)) * HW0);
        const float4* fp1 = fp0 + (HW0 / 4);
        const float4* ap = (const float4*)satt;
#pragma unroll
        for (int k = 0; k < 7; k++) {
            int i = lane + 32 * k;
            if (i < HW0 / 4) {
                float4 v0 = fp0[i], v1 = fp1[i], a = ap[i];
                acc0 = fmaf(v0.x, a.x, acc0);
                acc0 = fmaf(v0.y, a.y, acc0);
                acc0 = fmaf(v0.z, a.z, acc0);
                acc0 = fmaf(v0.w, a.w, acc0);
                acc1 = fmaf(v1.x, a.x, acc1);
                acc1 = fmaf(v1.y, a.y, acc1);
                acc1 = fmaf(v1.z, a.z, acc1);
                acc1 = fmaf(v1.w, a.w, acc1);
            }
        }
    } else if (l == 1) {
        if (t < HW1) {
            int ay = t / 14, ax = t % 14;
            int base = (2 * ay) * 28 + 2 * ax;
            float s = gs[base] + gs[base + 1] + gs[base + 28] + gs[base + 29];
            satt[t] = s * (1.f / 256.f);
        }
        __syncthreads();
        const float4* fp0 = (const float4*)(f1 + ((size_t)(b * C + c0)) * HW1);
        const float4* fp1 = fp0 + (HW1 / 4);
        const float4* ap = (const float4*)satt;
#pragma unroll
        for (int k = 0; k < 2; k++) {
            int i = lane + 32 * k;
            if (i < HW1 / 4) {
                float4 v0 = fp0[i], v1 = fp1[i], a = ap[i];
                acc0 = fmaf(v0.x, a.x, acc0);
                acc0 = fmaf(v0.y, a.y, acc0);
                acc0 = fmaf(v0.z, a.z, acc0);
                acc0 = fmaf(v0.w, a.w, acc0);
                acc1 = fmaf(v1.x, a.x, acc1);
                acc1 = fmaf(v1.y, a.y, acc1);
                acc1 = fmaf(v1.z, a.z, acc1);
                acc1 = fmaf(v1.w, a.w, acc1);
            }
        }
    } else {
        if (t < HW2) {
            int ay = t / 7, ax = t % 7;
            float s = 0.f;
#pragma unroll
            for (int iy = 0; iy < 4; iy++)
#pragma unroll
                for (int ix = 0; ix < 4; ix++)
                    s += gs[(4 * ay + iy) * 28 + 4 * ax + ix];
            satt[t] = s * (1.f / 1024.f);
        }
        __syncthreads();
        const float* fp0 = f2 + ((size_t)(b * C + c0)) * HW2;
        const float* fp1 = fp0 + HW2;
#pragma unroll
        for (int k = 0; k < 2; k++) {
            int i = lane + 32 * k;
            if (i < HW2) {
                float a = satt[i];
                acc0 = fmaf(fp0[i], a, acc0);
                acc1 = fmaf(fp1[i], a, acc1);
            }
        }
    }

#pragma unroll
    for (int o = 16; o > 0; o >>= 1) {
        acc0 += __shfl_xor_sync(0xffffffffu, acc0, o);
        acc1 += __shfl_xor_sync(0xffffffffu, acc1, o);
    }
    int base = (l * B + b) * C;
    if (lane == 0) {
        g_logits[base + c0] = acc0;
        g_logits[base + c0 + 1] = acc1;
    }
    __syncthreads();

    // ---- last-block softmax epilogue ----
    __shared__ int is_last;
    if (t == 0) {
        __threadfence();
        is_last = (atomicAdd(&g_cnt[l * B + b], 1) == (C / 16) - 1);
    }
    __syncthreads();
    if (!is_last) return;
    if (t == 0) g_cnt[l * B + b] = 0;   // reset for next graph replay

    __shared__ float red[8];
    __shared__ float smax, ssum;
    float x0 = g_logits[base + t];
    float x1 = g_logits[base + t + 256];
    float m = fmaxf(x0, x1);
#pragma unroll
    for (int o = 16; o > 0; o >>= 1) m = fmaxf(m, __shfl_xor_sync(0xffffffffu, m, o));
    if (lane == 0) red[warp] = m;
    __syncthreads();
    if (t == 0) {
        float mm = red[0];
#pragma unroll
        for (int i = 1; i < 8; i++) mm = fmaxf(mm, red[i]);
        smax = mm;
    }
    __syncthreads();
    float e0 = __expf(x0 - smax), e1 = __expf(x1 - smax);
    float s = e0 + e1;
#pragma unroll
    for (int o = 16; o > 0; o >>= 1) s += __shfl_xor_sync(0xffffffffu, s, o);
    if (lane == 0) red[warp] = s;
    __syncthreads();
    if (t == 0) {
        float ss = 0.f;
#pragma unroll
        for (int i = 0; i < 8; i++) ss += red[i];
        ssum = ss;
    }
    __syncthreads();
    float inv = __fdividef(1.f, ssum);
    g_weights[base + t] = e0 * inv;
    g_weights[base + t + 256] = e1 * inv;
}

// ---------------- K3: pure streaming scale, warp-per-row -----------------
__global__ void scale_kernel(const float* __restrict__ f0,
                             const float* __restrict__ f1,
                             const float* __restrict__ f2,
                             float* __restrict__ out) {
    int l = blockIdx.y;
    int warp = threadIdx.x >> 5, lane = threadIdx.x & 31;
    int row = blockIdx.x * 16 + warp;   // 0 .. B*C-1
    int b = row >> 9, c = row & (C - 1);
    float w = __ldg(&g_weights[(l * B + b) * C + c]);

    if (l == 0) {
        const float4* src = (const float4*)(f0 + (size_t)row * HW0);
        float4* dst = (float4*)(out + (size_t)b * OUT_ROW + (size_t)c * HW0);
#pragma unroll
        for (int k = 0; k < 7; k++) {
            int i = lane + 32 * k;
            if (i < HW0 / 4) {
                float4 v = src[i];
                v.x *= w; v.y *= w; v.z *= w; v.w *= w;
                __stcs(&dst[i], v);
            }
        }
    } else if (l == 1) {
        const float4* src = (const float4*)(f1 + (size_t)row * HW1);
        float4* dst = (float4*)(out + (size_t)b * OUT_ROW + OUT_OFF1 + (size_t)c * HW1);
#pragma unroll
        for (int k = 0; k < 2; k++) {
            int i = lane + 32 * k;
            if (i < HW1 / 4) {
                float4 v = src[i];
                v.x *= w; v.y *= w; v.z *= w; v.w *= w;
                __stcs(&dst[i], v);
            }
        }
    } else {
        const float* src = f2 + (size_t)row * HW2;
        float* dst = out + (size_t)b * OUT_ROW + OUT_OFF2 + (size_t)c * HW2;
#pragma unroll
        for (int k = 0; k < 2; k++) {
            int i = lane + 32 * k;
            if (i < HW2) __stcs(&dst[i], src[i] * w);
        }
    }
}

extern "C" void kernel_launch(void* const* d_in, const int* in_sizes, int n_in,
                              void* d_out, int out_size) {
    const float* confs = (const float*)d_in[0];
    const float* boxes = (const float*)d_in[1];
    const float* f0 = (const float*)d_in[2];
    const float* f1 = (const float*)d_in[3];
    const float* f2 = (const float*)d_in[4];
    float* out = (float*)d_out;

    tile_kernel<<<dim3(28, B), 256>>>(confs, boxes);
    logits_kernel<<<dim3(C / 16, B, 3), 256>>>(f0, f1, f2);
    scale_kernel<<<dim3(B * C / 16, 3), 512>>>(f0, f1, f2, out);
}

// round 14
// speedup vs baseline: 1.8901x; 1.0125x over previous
#include <cuda_runtime.h>
#include <math.h>

#define B 16
#define N 32
#define C 512
#define FEAT 224

#define HW0 784
#define HW1 196
#define HW2 49
#define OUT_ROW (C*(HW0+HW1+HW2))
#define OUT_OFF1 (C*HW0)         // 401408
#define OUT_OFF2 (C*(HW0+HW1))   // 501760

// ---------------- scratch (no allocations allowed) ----------------
__device__ float g_sum28[B][HW0];   // per-8x8-tile sum of sigmoid
__device__ float g_logits[3 * B * C];
__device__ float g_weights[3 * B * C];
__device__ int   g_cnt[3 * B];      // zero-init; reset by last block each run

// ---------------- K1: column-per-thread tile kernel ----------------------
// grid = (28 bands, B), 256 threads. Thread t<224 owns pixel column t:
// builds its column mask locally (no sync chain), iterates the band's 8
// rows with mask-change memoization (~3.3 sigmoids/thread), reduces within
// 8-lane groups, one atomicAdd per group into the 28 tile sums.
__global__ void tile_kernel(const float* __restrict__ confs,
                            const float* __restrict__ boxes) {
    int band = blockIdx.x, b = blockIdx.y;
    int t = threadIdx.x;
    int lane = t & 31;

    __shared__ int sbx[N * 4];
    __shared__ float sconf[N];
    __shared__ unsigned rm8[8];
    __shared__ float stile[28];

    if (t < N * 4) sbx[t] = (int)floorf(boxes[b * N * 4 + t] * (float)FEAT);
    if (t < N) sconf[t] = confs[b * N + t];
    if (t < 28) stile[t] = 0.f;
    __syncthreads();

    // band row masks (8 threads) -- parallel with column masks below
    if (t < 8) {
        int y = band * 8 + t;
        unsigned rm = 0;
#pragma unroll
        for (int n = 0; n < N; n++)
            rm |= (unsigned)(y >= sbx[4 * n + 1] && y < sbx[4 * n + 3]) << n;
        rm8[t] = rm;
    }

    // column mask for this thread's pixel column (broadcast LDS reads)
    unsigned cmask = 0;
    if (t < FEAT) {
#pragma unroll
        for (int n = 0; n < N; n++)
            cmask |= (unsigned)(t >= sbx[4 * n] && t < sbx[4 * n + 2]) << n;
    }
    __syncthreads();

    if (t < FEAT) {
        float acc = 0.f;
        unsigned prev = 0xffffffffu;
        float sg = 0.f;
#pragma unroll
        for (int i = 0; i < 8; i++) {
            unsigned m = rm8[i] & cmask;
            if (m != prev) {
                float v = 0.f;
                unsigned mm = m;
                while (mm) {
                    int j = __ffs(mm) - 1;
                    v += sconf[j];
                    mm &= mm - 1;
                }
                sg = __fdividef(1.f, 1.f + __expf(-v));
                prev = m;
            }
            acc += sg;
        }
        // segmented reduction: 8 consecutive lanes share one tile cell
        acc += __shfl_xor_sync(0xffffffffu, acc, 4);
        acc += __shfl_xor_sync(0xffffffffu, acc, 2);
        acc += __shfl_xor_sync(0xffffffffu, acc, 1);
        if ((lane & 7) == 0) atomicAdd(&stile[t >> 3], acc);
    }
    __syncthreads();
    if (t < 28) g_sum28[b][band * 28 + t] = stile[t];
}

// -------- K2: logits (2 channels/warp) + last-block softmax epilogue ------
// grid = (C/16, B, 3), 256 threads = 8 warps; each warp does 2 channels.
__global__ void logits_kernel(const float* __restrict__ f0,
                              const float* __restrict__ f1,
                              const float* __restrict__ f2) {
    int l = blockIdx.z, b = blockIdx.y;
    __shared__ __align__(16) float satt[HW0];

    int warp = threadIdx.x >> 5, lane = threadIdx.x & 31;
    int c0 = blockIdx.x * 16 + warp * 2;
    int t = threadIdx.x;
    float acc0 = 0.f, acc1 = 0.f;
    const float* gs = g_sum28[b];

    if (l == 0) {
        for (int i = t; i < HW0; i += 256) satt[i] = gs[i] * (1.f / 64.f);
        __syncthreads();
        const float4* fp0 = (const float4*)(f0 + ((size_t)(b * C + c0)) * HW0);
        const float4* fp1 = fp0 + (HW0 / 4);
        const float4* ap = (const float4*)satt;
#pragma unroll
        for (int k = 0; k < 7; k++) {
            int i = lane + 32 * k;
            if (i < HW0 / 4) {
                float4 v0 = fp0[i], v1 = fp1[i], a = ap[i];
                acc0 = fmaf(v0.x, a.x, acc0);
                acc0 = fmaf(v0.y, a.y, acc0);
                acc0 = fmaf(v0.z, a.z, acc0);
                acc0 = fmaf(v0.w, a.w, acc0);
                acc1 = fmaf(v1.x, a.x, acc1);
                acc1 = fmaf(v1.y, a.y, acc1);
                acc1 = fmaf(v1.z, a.z, acc1);
                acc1 = fmaf(v1.w, a.w, acc1);
            }
        }
    } else if (l == 1) {
        if (t < HW1) {
            int ay = t / 14, ax = t % 14;
            int base = (2 * ay) * 28 + 2 * ax;
            float s = gs[base] + gs[base + 1] + gs[base + 28] + gs[base + 29];
            satt[t] = s * (1.f / 256.f);
        }
        __syncthreads();
        const float4* fp0 = (const float4*)(f1 + ((size_t)(b * C + c0)) * HW1);
        const float4* fp1 = fp0 + (HW1 / 4);
        const float4* ap = (const float4*)satt;
#pragma unroll
        for (int k = 0; k < 2; k++) {
            int i = lane + 32 * k;
            if (i < HW1 / 4) {
                float4 v0 = fp0[i], v1 = fp1[i], a = ap[i];
                acc0 = fmaf(v0.x, a.x, acc0);
                acc0 = fmaf(v0.y, a.y, acc0);
                acc0 = fmaf(v0.z, a.z, acc0);
                acc0 = fmaf(v0.w, a.w, acc0);
                acc1 = fmaf(v1.x, a.x, acc1);
                acc1 = fmaf(v1.y, a.y, acc1);
                acc1 = fmaf(v1.z, a.z, acc1);
                acc1 = fmaf(v1.w, a.w, acc1);
            }
        }
    } else {
        if (t < HW2) {
            int ay = t / 7, ax = t % 7;
            float s = 0.f;
#pragma unroll
            for (int iy = 0; iy < 4; iy++)
#pragma unroll
                for (int ix = 0; ix < 4; ix++)
                    s += gs[(4 * ay + iy) * 28 + 4 * ax + ix];
            satt[t] = s * (1.f / 1024.f);
        }
        __syncthreads();
        const float* fp0 = f2 + ((size_t)(b * C + c0)) * HW2;
        const float* fp1 = fp0 + HW2;
#pragma unroll
        for (int k = 0; k < 2; k++) {
            int i = lane + 32 * k;
            if (i < HW2) {
                float a = satt[i];
                acc0 = fmaf(fp0[i], a, acc0);
                acc1 = fmaf(fp1[i], a, acc1);
            }
        }
    }

#pragma unroll
    for (int o = 16; o > 0; o >>= 1) {
        acc0 += __shfl_xor_sync(0xffffffffu, acc0, o);
        acc1 += __shfl_xor_sync(0xffffffffu, acc1, o);
    }
    int base = (l * B + b) * C;
    if (lane == 0) {
        g_logits[base + c0] = acc0;
        g_logits[base + c0 + 1] = acc1;
    }
    __syncthreads();

    // ---- last-block softmax epilogue ----
    __shared__ int is_last;
    if (t == 0) {
        __threadfence();
        is_last = (atomicAdd(&g_cnt[l * B + b], 1) == (C / 16) - 1);
    }
    __syncthreads();
    if (!is_last) return;
    if (t == 0) g_cnt[l * B + b] = 0;   // reset for next graph replay

    __shared__ float red[8];
    __shared__ float smax, ssum;
    float x0 = g_logits[base + t];
    float x1 = g_logits[base + t + 256];
    float m = fmaxf(x0, x1);
#pragma unroll
    for (int o = 16; o > 0; o >>= 1) m = fmaxf(m, __shfl_xor_sync(0xffffffffu, m, o));
    if (lane == 0) red[warp] = m;
    __syncthreads();
    if (t == 0) {
        float mm = red[0];
#pragma unroll
        for (int i = 1; i < 8; i++) mm = fmaxf(mm, red[i]);
        smax = mm;
    }
    __syncthreads();
    float e0 = __expf(x0 - smax), e1 = __expf(x1 - smax);
    float s = e0 + e1;
#pragma unroll
    for (int o = 16; o > 0; o >>= 1) s += __shfl_xor_sync(0xffffffffu, s, o);
    if (lane == 0) red[warp] = s;
    __syncthreads();
    if (t == 0) {
        float ss = 0.f;
#pragma unroll
        for (int i = 0; i < 8; i++) ss += red[i];
        ssum = ss;
    }
    __syncthreads();
    float inv = __fdividef(1.f, ssum);
    g_weights[base + t] = e0 * inv;
    g_weights[base + t + 256] = e1 * inv;
}

// ---------------- K3: pure streaming scale, warp-per-row -----------------
__global__ void scale_kernel(const float* __restrict__ f0,
                             const float* __restrict__ f1,
                             const float* __restrict__ f2,
                             float* __restrict__ out) {
    int l = blockIdx.y;
    int warp = threadIdx.x >> 5, lane = threadIdx.x & 31;
    int row = blockIdx.x * 16 + warp;   // 0 .. B*C-1
    int b = row >> 9, c = row & (C - 1);
    float w = __ldg(&g_weights[(l * B + b) * C + c]);

    if (l == 0) {
        const float4* src = (const float4*)(f0 + (size_t)row * HW0);
        float4* dst = (float4*)(out + (size_t)b * OUT_ROW + (size_t)c * HW0);
#pragma unroll
        for (int k = 0; k < 7; k++) {
            int i = lane + 32 * k;
            if (i < HW0 / 4) {
                float4 v = src[i];
                v.x *= w; v.y *= w; v.z *= w; v.w *= w;
                __stcs(&dst[i], v);
            }
        }
    } else if (l == 1) {
        const float4* src = (const float4*)(f1 + (size_t)row * HW1);
        float4* dst = (float4*)(out + (size_t)b * OUT_ROW + OUT_OFF1 + (size_t)c * HW1);
#pragma unroll
        for (int k = 0; k < 2; k++) {
            int i = lane + 32 * k;
            if (i < HW1 / 4) {
                float4 v = src[i];
                v.x *= w; v.y *= w; v.z *= w; v.w *= w;
                __stcs(&dst[i], v);
            }
        }
    } else {
        const float* src = f2 + (size_t)row * HW2;
        float* dst = out + (size_t)b * OUT_ROW + OUT_OFF2 + (size_t)c * HW2;
#pragma unroll
        for (int k = 0; k < 2; k++) {
            int i = lane + 32 * k;
            if (i < HW2) __stcs(&dst[i], src[i] * w);
        }
    }
}

extern "C" void kernel_launch(void* const* d_in, const int* in_sizes, int n_in,
                              void* d_out, int out_size) {
    const float* confs = (const float*)d_in[0];
    const float* boxes = (const float*)d_in[1];
    const float* f0 = (const float*)d_in[2];
    const float* f1 = (const float*)d_in[3];
    const float* f2 = (const float*)d_in[4];
    float* out = (float*)d_out;

    tile_kernel<<<dim3(28, B), 256>>>(confs, boxes);
    logits_kernel<<<dim3(C / 16, B, 3), 256>>>(f0, f1, f2);
    scale_kernel<<<dim3(B * C / 16, 3), 512>>>(f0, f1, f2, out);
}